// round 9
// baseline (speedup 1.0000x reference)
#include <cuda_runtime.h>
#include <cstdint>

#define TT 1024
#define BB 128
#define CC 256
#define SS 128
#define NTHR 256        // 8 warps, 2 per SMSP (balanced)
#define NW 8
#define WIN 16          // steps per sync window == halo overlap 32 / 2 states per step
#define LOG2E 1.4426950408889634f
#define LN2F  0.6931471805599453f
#define NEG2  (-1.0e9f)

__device__ float g_loss[BB];
__device__ int   g_done;          // zero-init; nets to zero every launch

static __device__ __forceinline__ float fexp2(float x){ float y; asm("ex2.approx.ftz.f32 %0, %1;" : "=f"(y) : "f"(x)); return y; }
static __device__ __forceinline__ float flog2(float x){ float y; asm("lg2.approx.f32 %0, %1;" : "=f"(y) : "f"(x)); return y; }
static __device__ __forceinline__ void cp16(unsigned dst, const float* src){
  asm volatile("cp.async.cg.shared.global [%0], [%1], 16;" :: "r"(dst), "l"(src));
}
static __device__ __forceinline__ void cp_commit(){ asm volatile("cp.async.commit_group;"); }
template<int N> static __device__ __forceinline__ void cp_wait(){ asm volatile("cp.async.wait_group %0;" :: "n"(N)); }

__global__ void __launch_bounds__(NTHR, 1) ctc_fwd(
    const float* __restrict__ lp, const int* __restrict__ y,
    const int* __restrict__ ilen, const int* __restrict__ tlen,
    float* __restrict__ out)
{
  __shared__ __align__(16) float rows[2 * WIN][CC]; // 32KB emission row ring, 2 windows
  __shared__ float alphA[292];                      // alpha exchange, double-buffered
  __shared__ float alphB[292];
  __shared__ float red[NW];
  __shared__ int   lastblk;

  const int b    = blockIdx.x;
  const int tid  = threadIdx.x;
  const int w    = tid >> 5;
  const int lane = tid & 31;
  const int len  = ilen[b];
  const int tl   = tlen[b];

  // Strips of 64 states, stride 32: warp w covers [32w, 32w+64)
  const int bw = 32 * w;
  const int s0 = bw + 2 * lane;          // even state (blank)
  const int s1 = s0 + 1;                 // odd state (label)
  const int ow_lo = w ? bw + 32 : 0;     // owned: w0 [0,64), else [32w+32, 32w+64)
  const bool ow0 = (s0 >= ow_lo);
  const bool ow1 = (s1 >= ow_lo);
  const bool lowcut = (w == 0) & (lane == 0);   // state 0 has no s-1 (even path only)

  // label class + skip flag for the odd state
  int idx  = s0 >> 1;                    // label index of s1
  int idxc = idx < SS ? idx : SS - 1;
  int im1  = idxc >= 1 ? idxc - 1 : 0;
  int cls  = y[b * SS + idxc];
  int clsp = y[b * SS + im1];
  bool skipok = (idx >= 1) && (idx < SS) && (cls != clsp);

  const float* gb = lp + (size_t)b * CC;
  const unsigned rows_u = (unsigned)__cvta_generic_to_shared(&rows[0][0]);

  // issue one 16-row window as one commit group (1024 coalesced 16B chunks)
  auto issue_win = [&](int wt) {
    int bslot = ((wt / WIN) & 1) * WIN;
    #pragma unroll
    for (int k = 0; k < 4; ++k) {
      int c = tid + k * NTHR;            // 0..1023
      int r   = c >> 6;
      int off = (c & 63) * 16;
      int row = wt + r;
      if (row < TT)
        cp16(rows_u + (unsigned)((bslot + r) * (CC * 4) + off),
             gb + (size_t)row * (BB * CC) + (off >> 2));
    }
    cp_commit();
  };

  issue_win(0);
  cp_wait<0>();
  __syncthreads();

  // t=0 init (log2 domain): only global states 0 and 1 reachable
  float a0 = NEG2, a1 = NEG2;
  if (lowcut) {
    a0 = rows[0][0]   * LOG2E;
    a1 = rows[0][cls] * LOG2E;
  }

  int wi = 0;
  for (int wt = 0; wt < len; wt += WIN, ++wi) {
    float* cur = (wi & 1) ? alphB : alphA;
    const int ws = (wi & 1) * WIN;

    // publish owned alpha_(wt-1) (t=0 init for window 0)
    if (ow0) cur[s0] = a0;
    if (ow1) cur[s1] = a1;

    cp_wait<0>();              // window wi resident (issued after previous barrier)
    __syncthreads();           // alpha publish + rows visibility

    issue_win(wt + WIN);       // other slot; its old readers all passed the barrier above

    // refresh full strip (fresh halo from neighbors' owned partitions)
    a0 = cur[s0];
    a1 = cur[s1];

    // emission registers for step wt (off the steady-state chain)
    float eb = rows[ws][0]   * LOG2E;
    float ec = rows[ws][cls] * LOG2E;

    #pragma unroll
    for (int j = 0; j < WIN; ++j) {
      const int t = wt + j;
      // prefetch next step's emissions first: LDS latency overlaps this step's chain
      float ebn = eb, ecn = ec;
      if (j + 1 < WIN) {
        ebn = rows[ws + j + 1][0]   * LOG2E;
        ecn = rows[ws + j + 1][cls] * LOG2E;
      }
      if (t >= 1 && t < len) {
        float sh = __shfl_up_sync(0xffffffffu, a1, 1);  // alpha[s0-1] == alpha[s1-2]
        // even (blank): lse2 with max-trick (1 EX2 + 1 LG2)
        float she = lowcut ? NEG2 : sh;
        float m0 = fmaxf(a0, she);
        float n0 = fminf(a0, she);
        float a0n = m0 + flog2(1.0f + fexp2(n0 - m0)) + eb;
        // odd: plain 3-exp lse3 (no select network on the chain)
        float sh2 = skipok ? sh : NEG2;
        float m1  = fmaxf(a1, fmaxf(a0, sh2));
        float sum = fexp2(a1 - m1) + fexp2(a0 - m1) + fexp2(sh2 - m1);
        float a1n = m1 + flog2(sum) + ec;
        a0 = a0n;
        a1 = a1n;
      }
      eb = ebn;
      ec = ecn;
    }
  }

  // final: stage alpha_(len-1), extract loss
  __syncthreads();
  if (ow0) alphA[s0] = a0;
  if (ow1) alphA[s1] = a1;
  __syncthreads();

  if (tid == 0) {
    float ahi = alphA[2 * tl];
    float alo = alphA[2 * tl - 1];
    float m  = fmaxf(ahi, alo);
    float mn = fminf(ahi, alo);
    float ll2 = m + flog2(1.0f + fexp2(mn - m));
    float loss = -ll2 * LN2F;
    if (!(loss < 0.5e9f)) loss = 0.f;    // zero_infinity (also inf/nan)
    g_loss[b] = loss / (float)tl;
    __threadfence();
    int old = atomicAdd(&g_done, 1);
    int isl = (old == BB - 1);
    if (isl) g_done = 0;                 // reset for next graph replay
    lastblk = isl;
  }
  __syncthreads();

  if (lastblk) {                         // fused mean over batches in last block
    __threadfence();
    float v = (tid < BB) ? g_loss[tid] : 0.f;
    #pragma unroll
    for (int o = 16; o > 0; o >>= 1) v += __shfl_down_sync(0xffffffffu, v, o);
    if (lane == 0) red[w] = v;
    __syncthreads();
    if (tid == 0) {
      float sum = 0.f;
      #pragma unroll
      for (int i = 0; i < NW; ++i) sum += red[i];
      out[0] = sum * (1.0f / (float)BB);
    }
  }
}

extern "C" void kernel_launch(void* const* d_in, const int* in_sizes, int n_in,
                              void* d_out, int out_size)
{
  const float* lp = (const float*)d_in[0];
  const int*   yy = (const int*)  d_in[1];
  const int*   il = (const int*)  d_in[2];
  const int*   tl = (const int*)  d_in[3];
  ctc_fwd<<<BB, NTHR>>>(lp, yy, il, tl, (float*)d_out);
}

// round 11
// speedup vs baseline: 1.5209x; 1.5209x over previous
#include <cuda_runtime.h>
#include <cstdint>

#define TT 1024
#define BB 128
#define CC 256
#define SS 128
#define NTHR 192        // 6 warps (proven R6 layout)
#define WIN 12          // steps per sync window == halo overlap 24 / 2 states per step
#define LOG2E 1.4426950408889634f
#define LN2F  0.6931471805599453f
#define NEG2  (-1.0e9f)

__device__ float g_loss[BB];
__device__ int   g_done;          // zero-init; nets to zero every launch

static __device__ __forceinline__ float fexp2(float x){ float y; asm("ex2.approx.ftz.f32 %0, %1;" : "=f"(y) : "f"(x)); return y; }
static __device__ __forceinline__ float flog2(float x){ float y; asm("lg2.approx.f32 %0, %1;" : "=f"(y) : "f"(x)); return y; }
static __device__ __forceinline__ void cp16(unsigned dst, const float* src){
  asm volatile("cp.async.cg.shared.global [%0], [%1], 16;" :: "r"(dst), "l"(src));
}
static __device__ __forceinline__ void cp_commit(){ asm volatile("cp.async.commit_group;"); }
template<int N> static __device__ __forceinline__ void cp_wait(){ asm volatile("cp.async.wait_group %0;" :: "n"(N)); }

__global__ void __launch_bounds__(NTHR, 1) ctc_fwd(
    const float* __restrict__ lp, const int* __restrict__ y,
    const int* __restrict__ ilen, const int* __restrict__ tlen,
    float* __restrict__ out)
{
  __shared__ __align__(16) float rows[2 * WIN][CC]; // 24KB emission row ring, 2 windows
  __shared__ float alphA[280];                      // alpha exchange, double-buffered
  __shared__ float alphB[280];
  __shared__ float red[8];
  __shared__ int   lastblk;

  const int b    = blockIdx.x;
  const int tid  = threadIdx.x;
  const int w    = tid >> 5;
  const int lane = tid & 31;
  const int len  = ilen[b];
  const int tl   = tlen[b];

  const int bw = 40 * w;                 // strip base (even state)
  const int s0 = bw + 2 * lane;          // even state (blank)
  const int s1 = s0 + 1;                 // odd state (label)
  const int own_lo = w ? bw + 24 : 0;    // owned partition: [own_lo, bw+64)
  const bool ow0 = (s0 >= own_lo);
  const bool ow1 = (s1 >= own_lo);
  const bool lowcut = (w == 0) & (lane == 0);   // state 0 has no s-1 (even path only)

  // label class + skip flag for the odd state
  int idx  = s0 >> 1;                    // label index of s1
  int idxc = idx < SS ? idx : SS - 1;
  int im1  = idxc >= 1 ? idxc - 1 : 0;
  int cls  = y[b * SS + idxc];
  int clsp = y[b * SS + im1];
  bool skipok = (idx >= 1) && (idx < SS) && (cls != clsp);

  const float* gb = lp + (size_t)b * CC;
  const unsigned rows_u = (unsigned)__cvta_generic_to_shared(&rows[0][0]);

  // issue one 12-row window as one commit group (768 coalesced 16B chunks)
  auto issue_win = [&](int wt) {
    int bslot = ((wt / WIN) & 1) * WIN;
    #pragma unroll
    for (int k = 0; k < 4; ++k) {
      int c = tid + k * NTHR;            // 0..767
      int r   = c >> 6;
      int off = (c & 63) * 16;
      int row = wt + r;
      if (row < TT)
        cp16(rows_u + (unsigned)((bslot + r) * (CC * 4) + off),
             gb + (size_t)row * (BB * CC) + (off >> 2));
    }
    cp_commit();
  };

  issue_win(0);
  cp_wait<0>();
  __syncthreads();

  // t=0 init (log2 domain): only global states 0 and 1 reachable
  float a0 = NEG2, a1 = NEG2;
  if (lowcut) {
    a0 = rows[0][0]   * LOG2E;
    a1 = rows[0][cls] * LOG2E;
  }

  int wi = 0;
  for (int wt = 0; wt < len; wt += WIN, ++wi) {
    float* cur = (wi & 1) ? alphB : alphA;
    const int ws = (wi & 1) * WIN;

    // publish owned alpha_(wt-1) (t=0 init for window 0)
    if (ow0) cur[s0] = a0;
    if (ow1) cur[s1] = a1;

    cp_wait<0>();              // window wi resident (issued after previous barrier)
    __syncthreads();           // alpha publish + rows visibility

    issue_win(wt + WIN);       // other slot; its old readers all passed the barrier above

    // refresh full strip (fresh halo from neighbors' owned partitions)
    a0 = cur[s0];
    a1 = cur[s1];

    // Preload ALL window emissions into registers: gather LDS off the step chain.
    float eb[WIN], ec[WIN];
    #pragma unroll
    for (int j = 0; j < WIN; ++j) {
      eb[j] = rows[ws + j][0]   * LOG2E;   // broadcast (conflict-free)
      ec[j] = rows[ws + j][cls] * LOG2E;   // per-lane gather
    }

    #pragma unroll
    for (int j = 0; j < WIN; ++j) {
      const int t = wt + j;
      if (t >= 1 && t < len) {
        float sh = __shfl_up_sync(0xffffffffu, a1, 1);  // alpha[s0-1] == alpha[s1-2]
        // even (blank): lse2 with max-trick (1 EX2 + 1 LG2)
        float she = lowcut ? NEG2 : sh;
        float m0 = fmaxf(a0, she);
        float n0 = fminf(a0, she);
        float a0n = m0 + flog2(1.0f + fexp2(n0 - m0)) + eb[j];
        // odd: 3-exp lse3; share m0 (when skipok, fmax(a0, sh) == m0)
        float sh2 = skipok ? sh : NEG2;
        float m1  = fmaxf(a1, skipok ? m0 : a0);
        float sum = fexp2(a1 - m1) + fexp2(a0 - m1) + fexp2(sh2 - m1);
        float a1n = m1 + flog2(sum) + ec[j];
        a0 = a0n;
        a1 = a1n;
      }
    }
  }

  // final: stage alpha_(len-1), extract loss
  __syncthreads();
  if (ow0) alphA[s0] = a0;
  if (ow1) alphA[s1] = a1;
  __syncthreads();

  if (tid == 0) {
    float ahi = alphA[2 * tl];
    float alo = alphA[2 * tl - 1];
    float m  = fmaxf(ahi, alo);
    float mn = fminf(ahi, alo);
    float ll2 = m + flog2(1.0f + fexp2(mn - m));
    float loss = -ll2 * LN2F;
    if (!(loss < 0.5e9f)) loss = 0.f;    // zero_infinity (also inf/nan)
    g_loss[b] = loss / (float)tl;
    __threadfence();
    int old = atomicAdd(&g_done, 1);
    int isl = (old == BB - 1);
    if (isl) g_done = 0;                 // reset for next graph replay
    lastblk = isl;
  }
  __syncthreads();

  if (lastblk) {                         // fused mean over batches in last block
    __threadfence();
    float v = (tid < BB) ? g_loss[tid] : 0.f;
    #pragma unroll
    for (int o = 16; o > 0; o >>= 1) v += __shfl_down_sync(0xffffffffu, v, o);
    if (lane == 0 && w < 4) red[w] = v;
    __syncthreads();
    if (tid == 0) out[0] = (red[0] + red[1] + red[2] + red[3]) * (1.0f / (float)BB);
  }
}

extern "C" void kernel_launch(void* const* d_in, const int* in_sizes, int n_in,
                              void* d_out, int out_size)
{
  const float* lp = (const float*)d_in[0];
  const int*   yy = (const int*)  d_in[1];
  const int*   il = (const int*)  d_in[2];
  const int*   tl = (const int*)  d_in[3];
  ctc_fwd<<<BB, NTHR>>>(lp, yy, il, tl, (float*)d_out);
}

// round 12
// speedup vs baseline: 1.8297x; 1.2031x over previous
#include <cuda_runtime.h>
#include <cstdint>

#define TT 1024
#define BB 128
#define CC 256
#define SS 128
#define NTHR 192        // 6 warps (proven R6 layout)
#define WIN 12          // steps per sync window == halo overlap 24 / 2 states per step
#define LOG2E 1.4426950408889634f
#define LN2F  0.6931471805599453f
#define NEG2  (-1.0e9f)

__device__ float g_loss[BB];
__device__ int   g_done;          // zero-init; nets to zero every launch

static __device__ __forceinline__ float fexp2(float x){ float y; asm("ex2.approx.ftz.f32 %0, %1;" : "=f"(y) : "f"(x)); return y; }
static __device__ __forceinline__ float flog2(float x){ float y; asm("lg2.approx.f32 %0, %1;" : "=f"(y) : "f"(x)); return y; }
static __device__ __forceinline__ void cp16(unsigned dst, const float* src){
  asm volatile("cp.async.cg.shared.global [%0], [%1], 16;" :: "r"(dst), "l"(src));
}
static __device__ __forceinline__ void cp_commit(){ asm volatile("cp.async.commit_group;"); }
template<int N> static __device__ __forceinline__ void cp_wait(){ asm volatile("cp.async.wait_group %0;" :: "n"(N)); }

__global__ void __launch_bounds__(NTHR, 1) ctc_fwd(
    const float* __restrict__ lp, const int* __restrict__ y,
    const int* __restrict__ ilen, const int* __restrict__ tlen,
    float* __restrict__ out)
{
  __shared__ __align__(16) float rows[2 * WIN][CC]; // 24KB emission row ring, 2 windows
  __shared__ float alphA[280];                      // alpha exchange, double-buffered
  __shared__ float alphB[280];
  __shared__ float red[8];
  __shared__ int   lastblk;

  const int b    = blockIdx.x;
  const int tid  = threadIdx.x;
  const int w    = tid >> 5;
  const int lane = tid & 31;
  const int len  = ilen[b];
  const int tl   = tlen[b];

  const int bw = 40 * w;                 // strip base (even state)
  const int s0 = bw + 2 * lane;          // even state (blank)
  const int s1 = s0 + 1;                 // odd state (label)
  const int own_lo = w ? bw + 24 : 0;    // owned partition: [own_lo, bw+64)
  const bool ow0 = (s0 >= own_lo);
  const bool ow1 = (s1 >= own_lo);
  const bool lowcut = (w == 0) & (lane == 0);   // state 0 has no s-1 (even path only)

  // label class + skip flag for the odd state
  int idx  = s0 >> 1;                    // label index of s1
  int idxc = idx < SS ? idx : SS - 1;
  int im1  = idxc >= 1 ? idxc - 1 : 0;
  int cls  = y[b * SS + idxc];
  int clsp = y[b * SS + im1];
  bool skipok = (idx >= 1) && (idx < SS) && (cls != clsp);

  const float* gb = lp + (size_t)b * CC;
  const unsigned rows_u = (unsigned)__cvta_generic_to_shared(&rows[0][0]);

  // issue one 12-row window as one commit group (768 coalesced 16B chunks)
  auto issue_win = [&](int wt) {
    int bslot = ((wt / WIN) & 1) * WIN;
    #pragma unroll
    for (int k = 0; k < 4; ++k) {
      int c = tid + k * NTHR;            // 0..767
      int r   = c >> 6;
      int off = (c & 63) * 16;
      int row = wt + r;
      if (row < TT)
        cp16(rows_u + (unsigned)((bslot + r) * (CC * 4) + off),
             gb + (size_t)row * (BB * CC) + (off >> 2));
    }
    cp_commit();
  };

  // one unguarded recurrence step, emissions loaded inline (R6-proven pattern)
  auto step = [&](float& a0, float& a1, int slot) {
    float sh = __shfl_up_sync(0xffffffffu, a1, 1);    // alpha[s0-1] == alpha[s1-2]
    float she = lowcut ? NEG2 : sh;
    float m0 = fmaxf(a0, she);
    float n0 = fminf(a0, she);
    float a0n = m0 + flog2(1.0f + fexp2(n0 - m0)) + rows[slot][0] * LOG2E;
    float sh2 = skipok ? sh : NEG2;
    float m1  = fmaxf(a1, fmaxf(a0, sh2));
    float sum = fexp2(a1 - m1) + fexp2(a0 - m1) + fexp2(sh2 - m1);
    float a1n = m1 + flog2(sum) + rows[slot][cls] * LOG2E;
    a0 = a0n;
    a1 = a1n;
  };

  issue_win(0);
  cp_wait<0>();
  __syncthreads();

  // t=0 init (log2 domain): only global states 0 and 1 reachable
  float a0 = NEG2, a1 = NEG2;
  if (lowcut) {
    a0 = rows[0][0]   * LOG2E;
    a1 = rows[0][cls] * LOG2E;
  }

  // ---- window 0 (peeled): steps t=1..WIN-1, unguarded (len >= 768 > WIN) ----
  if (ow0) alphA[s0] = a0;
  if (ow1) alphA[s1] = a1;
  cp_wait<0>();
  __syncthreads();
  issue_win(WIN);
  a0 = alphA[s0];
  a1 = alphA[s1];
  #pragma unroll
  for (int j = 1; j < WIN; ++j) step(a0, a1, j);

  // ---- steady windows: all 12 steps valid, no guards ----
  int wi = 1;
  int wt = WIN;
  for (; wt + WIN <= len; wt += WIN, ++wi) {
    float* cur = (wi & 1) ? alphB : alphA;
    const int ws = (wi & 1) * WIN;
    if (ow0) cur[s0] = a0;
    if (ow1) cur[s1] = a1;
    cp_wait<0>();
    __syncthreads();
    issue_win(wt + WIN);
    a0 = cur[s0];
    a1 = cur[s1];
    #pragma unroll
    for (int j = 0; j < WIN; ++j) step(a0, a1, ws + j);
  }

  // ---- tail window: rem in [0, WIN) steps, runtime-bounded, body unguarded ----
  const int rem = len - wt;
  if (rem > 0) {
    float* cur = (wi & 1) ? alphB : alphA;
    const int ws = (wi & 1) * WIN;
    if (ow0) cur[s0] = a0;
    if (ow1) cur[s1] = a1;
    cp_wait<0>();
    __syncthreads();
    a0 = cur[s0];
    a1 = cur[s1];
    #pragma unroll 1
    for (int j = 0; j < rem; ++j) step(a0, a1, ws + j);
  }

  // final: stage alpha_(len-1), extract loss
  __syncthreads();
  if (ow0) alphA[s0] = a0;
  if (ow1) alphA[s1] = a1;
  __syncthreads();

  if (tid == 0) {
    float ahi = alphA[2 * tl];
    float alo = alphA[2 * tl - 1];
    float m  = fmaxf(ahi, alo);
    float mn = fminf(ahi, alo);
    float ll2 = m + flog2(1.0f + fexp2(mn - m));
    float loss = -ll2 * LN2F;
    if (!(loss < 0.5e9f)) loss = 0.f;    // zero_infinity (also inf/nan)
    g_loss[b] = loss / (float)tl;
    __threadfence();
    int old = atomicAdd(&g_done, 1);
    int isl = (old == BB - 1);
    if (isl) g_done = 0;                 // reset for next graph replay
    lastblk = isl;
  }
  __syncthreads();

  if (lastblk) {                         // fused mean over batches in last block
    __threadfence();
    float v = (tid < BB) ? g_loss[tid] : 0.f;
    #pragma unroll
    for (int o = 16; o > 0; o >>= 1) v += __shfl_down_sync(0xffffffffu, v, o);
    if (lane == 0 && w < 4) red[w] = v;
    __syncthreads();
    if (tid == 0) out[0] = (red[0] + red[1] + red[2] + red[3]) * (1.0f / (float)BB);
  }
}

extern "C" void kernel_launch(void* const* d_in, const int* in_sizes, int n_in,
                              void* d_out, int out_size)
{
  const float* lp = (const float*)d_in[0];
  const int*   yy = (const int*)  d_in[1];
  const int*   il = (const int*)  d_in[2];
  const int*   tl = (const int*)  d_in[3];
  ctc_fwd<<<BB, NTHR>>>(lp, yy, il, tl, (float*)d_out);
}

// round 13
// speedup vs baseline: 2.0082x; 1.0976x over previous
#include <cuda_runtime.h>
#include <cstdint>

#define TT 1024
#define BB 128
#define CC 256
#define SS 128
#define NTHR 192        // 6 warps (proven layout)
#define WIN 12          // steps per sync window == halo overlap 24 / 2 states per step
#define LOG2E 1.4426950408889634f
#define LN2F  0.6931471805599453f
#define NEG2  (-1.0e9f)

__device__ float g_loss[BB];
__device__ int   g_done;          // zero-init; nets to zero every launch

static __device__ __forceinline__ float fexp2(float x){ float y; asm("ex2.approx.ftz.f32 %0, %1;" : "=f"(y) : "f"(x)); return y; }
static __device__ __forceinline__ float flog2(float x){ float y; asm("lg2.approx.f32 %0, %1;" : "=f"(y) : "f"(x)); return y; }
static __device__ __forceinline__ void cp16(unsigned dst, const float* src){
  asm volatile("cp.async.cg.shared.global [%0], [%1], 16;" :: "r"(dst), "l"(src));
}
static __device__ __forceinline__ void cp_commit(){ asm volatile("cp.async.commit_group;"); }
template<int N> static __device__ __forceinline__ void cp_wait(){ asm volatile("cp.async.wait_group %0;" :: "n"(N)); }

__global__ void __launch_bounds__(NTHR, 1) ctc_fwd(
    const float* __restrict__ lp, const int* __restrict__ y,
    const int* __restrict__ ilen, const int* __restrict__ tlen,
    float* __restrict__ out)
{
  __shared__ __align__(16) float rows[2 * WIN][CC]; // 24KB emission row ring, 2 windows
  __shared__ float alphA[280];                      // alpha exchange, double-buffered
  __shared__ float alphB[280];
  __shared__ float red[8];
  __shared__ int   lastblk;

  const int b    = blockIdx.x;
  const int tid  = threadIdx.x;
  const int w    = tid >> 5;
  const int lane = tid & 31;
  const int len  = ilen[b];
  const int tl   = tlen[b];

  const int bw = 40 * w;                 // strip base (even state)
  const int s0 = bw + 2 * lane;          // even state (blank)
  const int s1 = s0 + 1;                 // odd state (label)
  const int own_lo = w ? bw + 24 : 0;    // owned partition: [own_lo, bw+64)
  const bool ow0 = (s0 >= own_lo);
  const bool ow1 = (s1 >= own_lo);
  const bool lowcut = (w == 0) & (lane == 0);   // state 0 has no s-1 (even path only)

  // label class + skip flag for the odd state
  int idx  = s0 >> 1;                    // label index of s1
  int idxc = idx < SS ? idx : SS - 1;
  int im1  = idxc >= 1 ? idxc - 1 : 0;
  int cls  = y[b * SS + idxc];
  int clsp = y[b * SS + im1];
  bool skipok = (idx >= 1) && (idx < SS) && (cls != clsp);

  const float* gb = lp + (size_t)b * CC;
  const unsigned rows_u = (unsigned)__cvta_generic_to_shared(&rows[0][0]);

  // issue one 12-row window as one commit group (768 coalesced 16B chunks)
  auto issue_win = [&](int wt) {
    int bslot = ((wt / WIN) & 1) * WIN;
    #pragma unroll
    for (int k = 0; k < 4; ++k) {
      int c = tid + k * NTHR;            // 0..767
      int r   = c >> 6;
      int off = (c & 63) * 16;
      int row = wt + r;
      if (row < TT)
        cp16(rows_u + (unsigned)((bslot + r) * (CC * 4) + off),
             gb + (size_t)row * (BB * CC) + (off >> 2));
    }
    cp_commit();
  };

  // one unguarded recurrence step; select-form lse3 (2 EX2), emit folded into max term
  auto step = [&](float& a0, float& a1, int slot) {
    float sh = __shfl_up_sync(0xffffffffu, a1, 1);    // alpha[s0-1] == alpha[s1-2]
    // even (blank): lse2
    float she = lowcut ? NEG2 : sh;
    float m0 = fmaxf(a0, she);
    float n0 = fminf(a0, she);
    float a0n = (m0 + rows[slot][0] * LOG2E) + flog2(1.0f + fexp2(n0 - m0));
    // odd: lse3 via FMNMX mid/min extraction (no predicates, 2 EX2)
    float sh2 = skipok ? sh : NEG2;
    float x  = fmaxf(a0, sh2);
    float yv = fminf(a0, sh2);
    float m1  = fmaxf(a1, x);
    float mid = fmaxf(fminf(a1, x), yv);
    float mn  = fminf(a1, yv);
    float sum = 1.0f + fexp2(mid - m1) + fexp2(mn - m1);
    float a1n = (m1 + rows[slot][cls] * LOG2E) + flog2(sum);
    a0 = a0n;
    a1 = a1n;
  };

  issue_win(0);
  cp_wait<0>();
  __syncthreads();

  // t=0 init (log2 domain): only global states 0 and 1 reachable
  float a0 = NEG2, a1 = NEG2;
  if (lowcut) {
    a0 = rows[0][0]   * LOG2E;
    a1 = rows[0][cls] * LOG2E;
  }

  // ---- window 0 (peeled): steps t=1..WIN-1, unguarded (len >= 768 > WIN) ----
  if (ow0) alphA[s0] = a0;
  if (ow1) alphA[s1] = a1;
  cp_wait<0>();
  __syncthreads();
  a0 = alphA[s0];
  a1 = alphA[s1];
  issue_win(WIN);
  #pragma unroll
  for (int j = 1; j < WIN; ++j) step(a0, a1, j);

  // ---- steady windows: all 12 steps valid, no guards ----
  int wi = 1;
  int wt = WIN;
  for (; wt + WIN <= len; wt += WIN, ++wi) {
    float* cur = (wi & 1) ? alphB : alphA;
    const int ws = (wi & 1) * WIN;
    if (ow0) cur[s0] = a0;
    if (ow1) cur[s1] = a1;
    cp_wait<0>();
    __syncthreads();
    a0 = cur[s0];                // strip reload first (critical path)
    a1 = cur[s1];
    issue_win(wt + WIN);         // then prefetch burst
    #pragma unroll
    for (int j = 0; j < WIN; ++j) step(a0, a1, ws + j);
  }

  // ---- tail window: rem in [0, WIN) steps, runtime-bounded, body unguarded ----
  const int rem = len - wt;
  if (rem > 0) {
    float* cur = (wi & 1) ? alphB : alphA;
    const int ws = (wi & 1) * WIN;
    if (ow0) cur[s0] = a0;
    if (ow1) cur[s1] = a1;
    cp_wait<0>();
    __syncthreads();
    a0 = cur[s0];
    a1 = cur[s1];
    #pragma unroll 1
    for (int j = 0; j < rem; ++j) step(a0, a1, ws + j);
  }

  // final: stage alpha_(len-1), extract loss
  __syncthreads();
  if (ow0) alphA[s0] = a0;
  if (ow1) alphA[s1] = a1;
  __syncthreads();

  if (tid == 0) {
    float ahi = alphA[2 * tl];
    float alo = alphA[2 * tl - 1];
    float m  = fmaxf(ahi, alo);
    float mn = fminf(ahi, alo);
    float ll2 = m + flog2(1.0f + fexp2(mn - m));
    float loss = -ll2 * LN2F;
    if (!(loss < 0.5e9f)) loss = 0.f;    // zero_infinity (also inf/nan)
    g_loss[b] = loss / (float)tl;
    __threadfence();
    int old = atomicAdd(&g_done, 1);
    int isl = (old == BB - 1);
    if (isl) g_done = 0;                 // reset for next graph replay
    lastblk = isl;
  }
  __syncthreads();

  if (lastblk) {                         // fused mean over batches in last block
    __threadfence();
    float v = (tid < BB) ? g_loss[tid] : 0.f;
    #pragma unroll
    for (int o = 16; o > 0; o >>= 1) v += __shfl_down_sync(0xffffffffu, v, o);
    if (lane == 0 && w < 4) red[w] = v;
    __syncthreads();
    if (tid == 0) out[0] = (red[0] + red[1] + red[2] + red[3]) * (1.0f / (float)BB);
  }
}

extern "C" void kernel_launch(void* const* d_in, const int* in_sizes, int n_in,
                              void* d_out, int out_size)
{
  const float* lp = (const float*)d_in[0];
  const int*   yy = (const int*)  d_in[1];
  const int*   il = (const int*)  d_in[2];
  const int*   tl = (const int*)  d_in[3];
  ctc_fwd<<<BB, NTHR>>>(lp, yy, il, tl, (float*)d_out);
}